// round 1
// baseline (speedup 1.0000x reference)
#include <cuda_runtime.h>

// Problem constants (fixed by the dataset): N=200000, E=6400000, F: 128 -> 8 -> 16
#define NMAX 200000
#define EMAX 6400000

// Scratch (no cudaMalloc allowed)
__device__ float g_dis[NMAX];        // degree, then deg^-1/2 in place
__device__ float g_h[NMAX * 8];      // x @ W1
__device__ float g_agg[NMAX * 8];    // layer-1 aggregation
__device__ float g_g[NMAX * 16];     // relu(agg+b1) @ W2
__device__ int   g_is64;             // edge_index dtype flag

// ---------------------------------------------------------------------------
// K0: detect whether edge_index is int64 or int32.
// If the data is int32, interpreting it as int64 packs two random node ids
// (lo, hi) into one value = lo + hi*2^32, which is >= N unless hi==0
// (probability ~5e-6 per sample). 8 samples all in [0,N) => int64.
__global__ void k_detect(const void* ei, int N) {
    if (threadIdx.x == 0 && blockIdx.x == 0) {
        const long long* p = (const long long*)ei;
        int is64 = 1;
#pragma unroll
        for (int i = 0; i < 8; i++) {
            long long v = p[i];
            if (v < 0 || v >= (long long)N) is64 = 0;
        }
        g_is64 = is64;
    }
}

__device__ __forceinline__ int load_idx(const void* ei, long long pos, int is64) {
    if (is64) return (int)((const long long*)ei)[pos];
    return ((const int*)ei)[pos];
}

// ---------------------------------------------------------------------------
// Degree: init to 1.0 (self loop), scatter +1 per edge dst, then rsqrt in place.
__global__ void k_deg_init(int N) {
    int i = blockIdx.x * blockDim.x + threadIdx.x;
    if (i < N) g_dis[i] = 1.0f;
}

__global__ void k_deg(const void* ei, int E) {
    int e = blockIdx.x * blockDim.x + threadIdx.x;
    if (e >= E) return;
    int is64 = g_is64;
    int d = load_idx(ei, (long long)E + e, is64);
    atomicAdd(&g_dis[d], 1.0f);
}

__global__ void k_rsqrt(int N) {
    int i = blockIdx.x * blockDim.x + threadIdx.x;
    if (i < N) g_dis[i] = rsqrtf(g_dis[i]);
}

// ---------------------------------------------------------------------------
// K3: h = x @ W1   (N x 128) @ (128 x 8). Warp per node; coalesced float4 reads.
__global__ void k_gemm1(const float* __restrict__ x, const float* __restrict__ W1, int N) {
    __shared__ float sW[128 * 8];
    for (int i = threadIdx.x; i < 128 * 8; i += blockDim.x) sW[i] = W1[i];
    __syncthreads();

    int gwarp  = (blockIdx.x * blockDim.x + threadIdx.x) >> 5;
    int lane   = threadIdx.x & 31;
    int nwarps = (gridDim.x * blockDim.x) >> 5;

    for (int n = gwarp; n < N; n += nwarps) {
        float4 xv = ((const float4*)(x + (long long)n * 128))[lane];
        float acc[8];
#pragma unroll
        for (int f = 0; f < 8; f++) acc[f] = 0.0f;
        const float* w = &sW[(lane * 4) * 8];
#pragma unroll
        for (int f = 0; f < 8; f++)
            acc[f] = xv.x * w[f] + xv.y * w[8 + f] + xv.z * w[16 + f] + xv.w * w[24 + f];
#pragma unroll
        for (int f = 0; f < 8; f++) {
#pragma unroll
            for (int off = 16; off; off >>= 1)
                acc[f] += __shfl_xor_sync(0xffffffffu, acc[f], off);
        }
        if (lane == 0) {
            float4 a = make_float4(acc[0], acc[1], acc[2], acc[3]);
            float4 b = make_float4(acc[4], acc[5], acc[6], acc[7]);
            float4* hp = (float4*)(g_h + (long long)n * 8);
            hp[0] = a;
            hp[1] = b;
        }
    }
}

// ---------------------------------------------------------------------------
// K4: agg1[i] = h[i] * dis[i]^2   (self-loop contribution)
__global__ void k_agg_init(int N) {
    int idx = blockIdx.x * blockDim.x + threadIdx.x;  // over N*2 float4s
    if (idx >= N * 2) return;
    int n = idx >> 1;
    float d = g_dis[n];
    float s = d * d;
    float4 v = ((const float4*)g_h)[idx];
    v.x *= s; v.y *= s; v.z *= s; v.w *= s;
    ((float4*)g_agg)[idx] = v;
}

__device__ __forceinline__ void red_v4(float* p, float a, float b, float c, float d) {
    asm volatile("red.global.add.v4.f32 [%0], {%1, %2, %3, %4};"
                 :: "l"(p), "f"(a), "f"(b), "f"(c), "f"(d) : "memory");
}

// K5: layer-1 edge scatter: agg1[dst] += h[src] * dis[src]*dis[dst]
__global__ void k_sc1(const void* ei, int E) {
    int e = blockIdx.x * blockDim.x + threadIdx.x;
    if (e >= E) return;
    int is64 = g_is64;
    int s = load_idx(ei, e, is64);
    int d = load_idx(ei, (long long)E + e, is64);
    float w = g_dis[s] * g_dis[d];
    const float4* hp = (const float4*)(g_h + (long long)s * 8);
    float4 a = hp[0], b = hp[1];
    float* o = g_agg + (long long)d * 8;
    red_v4(o,     a.x * w, a.y * w, a.z * w, a.w * w);
    red_v4(o + 4, b.x * w, b.y * w, b.z * w, b.w * w);
}

// ---------------------------------------------------------------------------
// K6: g = relu(agg1 + b1) @ W2 ; out = g * dis^2 + b2  (self-loop + bias fold)
__global__ void k_mid(const float* __restrict__ b1, const float* __restrict__ W2,
                      const float* __restrict__ b2, float* __restrict__ out, int N) {
    __shared__ float sW[8 * 16];
    __shared__ float sb1[8];
    __shared__ float sb2[16];
    if (threadIdx.x < 128) sW[threadIdx.x] = W2[threadIdx.x];
    if (threadIdx.x < 8)  sb1[threadIdx.x] = b1[threadIdx.x];
    if (threadIdx.x < 16) sb2[threadIdx.x] = b2[threadIdx.x];
    __syncthreads();

    int n = blockIdx.x * blockDim.x + threadIdx.x;
    if (n >= N) return;

    const float4* ap = (const float4*)(g_agg + (long long)n * 8);
    float4 u = ap[0], v = ap[1];
    float a[8];
    a[0] = fmaxf(u.x + sb1[0], 0.0f);
    a[1] = fmaxf(u.y + sb1[1], 0.0f);
    a[2] = fmaxf(u.z + sb1[2], 0.0f);
    a[3] = fmaxf(u.w + sb1[3], 0.0f);
    a[4] = fmaxf(v.x + sb1[4], 0.0f);
    a[5] = fmaxf(v.y + sb1[5], 0.0f);
    a[6] = fmaxf(v.z + sb1[6], 0.0f);
    a[7] = fmaxf(v.w + sb1[7], 0.0f);

    float o[16];
#pragma unroll
    for (int j = 0; j < 16; j++) o[j] = 0.0f;
#pragma unroll
    for (int k = 0; k < 8; k++) {
        float ak = a[k];
#pragma unroll
        for (int j = 0; j < 16; j++) o[j] = fmaf(ak, sW[k * 16 + j], o[j]);
    }

    float dis = g_dis[n];
    float s2 = dis * dis;
    float4* gp  = (float4*)(g_g + (long long)n * 16);
    float4* op  = (float4*)(out + (long long)n * 16);
#pragma unroll
    for (int q = 0; q < 4; q++) {
        float4 gv = make_float4(o[q * 4], o[q * 4 + 1], o[q * 4 + 2], o[q * 4 + 3]);
        gp[q] = gv;
        float4 ov = make_float4(gv.x * s2 + sb2[q * 4],
                                gv.y * s2 + sb2[q * 4 + 1],
                                gv.z * s2 + sb2[q * 4 + 2],
                                gv.w * s2 + sb2[q * 4 + 3]);
        op[q] = ov;
    }
}

// K8: layer-2 edge scatter: out[dst] += g[src] * dis[src]*dis[dst]
__global__ void k_sc2(const void* ei, float* __restrict__ out, int E) {
    int e = blockIdx.x * blockDim.x + threadIdx.x;
    if (e >= E) return;
    int is64 = g_is64;
    int s = load_idx(ei, e, is64);
    int d = load_idx(ei, (long long)E + e, is64);
    float w = g_dis[s] * g_dis[d];
    const float4* gp = (const float4*)(g_g + (long long)s * 16);
    float* o = out + (long long)d * 16;
#pragma unroll
    for (int q = 0; q < 4; q++) {
        float4 gv = gp[q];
        red_v4(o + q * 4, gv.x * w, gv.y * w, gv.z * w, gv.w * w);
    }
}

// ---------------------------------------------------------------------------
extern "C" void kernel_launch(void* const* d_in, const int* in_sizes, int n_in,
                              void* d_out, int out_size) {
    const float* x   = (const float*)d_in[0];
    const void*  ei  = d_in[1];
    const float* W1  = (const float*)d_in[2];
    const float* b1  = (const float*)d_in[3];
    const float* W2  = (const float*)d_in[4];
    const float* b2  = (const float*)d_in[5];
    float* out = (float*)d_out;

    int N = in_sizes[0] / 128;
    int E = in_sizes[1] / 2;

    const int T = 256;
    int nb_N   = (N + T - 1) / T;
    int nb_N2  = (N * 2 + T - 1) / T;
    int nb_E   = (E + T - 1) / T;
    int nb_W   = (N * 32 + T - 1) / T;  // warp per node

    k_detect<<<1, 32>>>(ei, N);
    k_deg_init<<<nb_N, T>>>(N);
    k_deg<<<nb_E, T>>>(ei, E);
    k_rsqrt<<<nb_N, T>>>(N);
    k_gemm1<<<nb_W, T>>>(x, W1, N);
    k_agg_init<<<nb_N2, T>>>(N);
    k_sc1<<<nb_E, T>>>(ei, E);
    k_mid<<<nb_N, T>>>(b1, W2, b2, out, N);
    k_sc2<<<nb_E, T>>>(ei, out, E);
}

// round 2
// speedup vs baseline: 1.1900x; 1.1900x over previous
#include <cuda_runtime.h>

// Problem constants (fixed by the dataset): N=200000, E=6400000, F: 128 -> 8 -> 16
#define NMAX 200000
#define EMAX 6400000

// Scratch (no cudaMalloc allowed)
__device__ float g_dis[NMAX];         // degree, then deg^-1/2 in place
__device__ float g_h[NMAX * 8];       // x @ W1
__device__ float g_agg[NMAX * 8];     // layer-1 aggregation
__device__ float g_r[NMAX * 8];       // relu(agg1 + b1)
__device__ float g_agg2[NMAX * 8];    // layer-2 aggregation (8-dim, pre-W2!)
__device__ int2  g_edge[EMAX];        // packed (src, dst) int32
__device__ int   g_is64;              // edge_index dtype flag

// ---------------------------------------------------------------------------
// K0: detect whether edge_index is int64 or int32.
// int32 data read as int64 packs two node ids: lo + hi*2^32 >= N unless hi==0
// (prob ~5e-6 per sample). 8 samples all in [0,N) => int64.
__global__ void k_detect(const void* ei, int N) {
    if (threadIdx.x == 0 && blockIdx.x == 0) {
        const long long* p = (const long long*)ei;
        int is64 = 1;
#pragma unroll
        for (int i = 0; i < 8; i++) {
            long long v = p[i];
            if (v < 0 || v >= (long long)N) is64 = 0;
        }
        g_is64 = is64;
    }
}

__global__ void k_deg_init(int N) {
    int i = blockIdx.x * blockDim.x + threadIdx.x;
    if (i < N) g_dis[i] = 1.0f;   // self-loop
}

// ---------------------------------------------------------------------------
// K1: convert indices to packed int2 once + degree scatter.
__global__ void k_convert_deg(const void* ei, int E) {
    int e = blockIdx.x * blockDim.x + threadIdx.x;
    if (e >= E) return;
    int is64 = g_is64;
    int s, d;
    if (is64) {
        s = (int)((const long long*)ei)[e];
        d = (int)((const long long*)ei)[(long long)E + e];
    } else {
        s = ((const int*)ei)[e];
        d = ((const int*)ei)[E + e];
    }
    g_edge[e] = make_int2(s, d);
    atomicAdd(&g_dis[d], 1.0f);
}

// ---------------------------------------------------------------------------
// K2: h = x @ W1 (N x 128)@(128 x 8), warp per node, coalesced float4 reads.
// Fused: dis = rsqrt(deg) in place (each node owned by exactly one warp),
// and agg1 self-loop init: agg1 = h * dis^2.
__global__ void k_gemm1(const float* __restrict__ x, const float* __restrict__ W1, int N) {
    __shared__ float sW[128 * 8];
    for (int i = threadIdx.x; i < 128 * 8; i += blockDim.x) sW[i] = W1[i];
    __syncthreads();

    int n    = (blockIdx.x * blockDim.x + threadIdx.x) >> 5;
    int lane = threadIdx.x & 31;
    if (n >= N) return;

    float4 xv = ((const float4*)(x + (long long)n * 128))[lane];
    float acc[8];
    const float* w = &sW[(lane * 4) * 8];
#pragma unroll
    for (int f = 0; f < 8; f++)
        acc[f] = xv.x * w[f] + xv.y * w[8 + f] + xv.z * w[16 + f] + xv.w * w[24 + f];
#pragma unroll
    for (int f = 0; f < 8; f++) {
#pragma unroll
        for (int off = 16; off; off >>= 1)
            acc[f] += __shfl_xor_sync(0xffffffffu, acc[f], off);
    }
    if (lane == 0) {
        float deg = g_dis[n];
        float r   = rsqrtf(deg);
        g_dis[n]  = r;                 // in place: deg -> deg^-1/2
        float s2  = r * r;
        float4 a = make_float4(acc[0], acc[1], acc[2], acc[3]);
        float4 b = make_float4(acc[4], acc[5], acc[6], acc[7]);
        float4* hp = (float4*)(g_h + (long long)n * 8);
        hp[0] = a; hp[1] = b;
        float4* ap = (float4*)(g_agg + (long long)n * 8);
        ap[0] = make_float4(a.x * s2, a.y * s2, a.z * s2, a.w * s2);
        ap[1] = make_float4(b.x * s2, b.y * s2, b.z * s2, b.w * s2);
    }
}

// ---------------------------------------------------------------------------
__device__ __forceinline__ void red_v4(float* p, float a, float b, float c, float d) {
    asm volatile("red.global.add.v4.f32 [%0], {%1, %2, %3, %4};"
                 :: "l"(p), "f"(a), "f"(b), "f"(c), "f"(d) : "memory");
}

// Shared 8-dim edge scatter body: dst_feat[d] += src_feat[s] * dis[s]*dis[d]
__device__ __forceinline__ void scatter8(const float* __restrict__ src_feat,
                                         float* __restrict__ dst_feat, int E) {
    int e = blockIdx.x * blockDim.x + threadIdx.x;
    if (e >= E) return;
    int2 sd = g_edge[e];
    float w = g_dis[sd.x] * g_dis[sd.y];
    const float4* hp = (const float4*)(src_feat + (long long)sd.x * 8);
    float4 a = hp[0], b = hp[1];
    float* o = dst_feat + (long long)sd.y * 8;
    red_v4(o,     a.x * w, a.y * w, a.z * w, a.w * w);
    red_v4(o + 4, b.x * w, b.y * w, b.z * w, b.w * w);
}

__global__ void k_sc1(int E) { scatter8(g_h, g_agg, E); }
__global__ void k_sc2(int E) { scatter8(g_r, g_agg2, E); }

// ---------------------------------------------------------------------------
// K3: r = relu(agg1 + b1); agg2 self-loop init: agg2 = r * dis^2. (8-dim)
__global__ void k_mid(const float* __restrict__ b1, int N) {
    __shared__ float sb1[8];
    if (threadIdx.x < 8) sb1[threadIdx.x] = b1[threadIdx.x];
    __syncthreads();

    int n = blockIdx.x * blockDim.x + threadIdx.x;
    if (n >= N) return;

    const float4* ap = (const float4*)(g_agg + (long long)n * 8);
    float4 u = ap[0], v = ap[1];
    float4 r0 = make_float4(fmaxf(u.x + sb1[0], 0.0f), fmaxf(u.y + sb1[1], 0.0f),
                            fmaxf(u.z + sb1[2], 0.0f), fmaxf(u.w + sb1[3], 0.0f));
    float4 r1 = make_float4(fmaxf(v.x + sb1[4], 0.0f), fmaxf(v.y + sb1[5], 0.0f),
                            fmaxf(v.z + sb1[6], 0.0f), fmaxf(v.w + sb1[7], 0.0f));
    float4* rp = (float4*)(g_r + (long long)n * 8);
    rp[0] = r0; rp[1] = r1;

    float dis = g_dis[n];
    float s2 = dis * dis;
    float4* a2 = (float4*)(g_agg2 + (long long)n * 8);
    a2[0] = make_float4(r0.x * s2, r0.y * s2, r0.z * s2, r0.w * s2);
    a2[1] = make_float4(r1.x * s2, r1.y * s2, r1.z * s2, r1.w * s2);
}

// ---------------------------------------------------------------------------
// K4: out = agg2 @ W2 + b2   (W2 commuted past the aggregation)
__global__ void k_out(const float* __restrict__ W2, const float* __restrict__ b2,
                      float* __restrict__ out, int N) {
    __shared__ float sW[8 * 16];
    __shared__ float sb2[16];
    if (threadIdx.x < 128) sW[threadIdx.x] = W2[threadIdx.x];
    if (threadIdx.x < 16) sb2[threadIdx.x] = b2[threadIdx.x];
    __syncthreads();

    int n = blockIdx.x * blockDim.x + threadIdx.x;
    if (n >= N) return;

    const float4* ap = (const float4*)(g_agg2 + (long long)n * 8);
    float4 u = ap[0], v = ap[1];
    float a[8] = {u.x, u.y, u.z, u.w, v.x, v.y, v.z, v.w};

    float o[16];
#pragma unroll
    for (int j = 0; j < 16; j++) o[j] = sb2[j];
#pragma unroll
    for (int k = 0; k < 8; k++) {
        float ak = a[k];
#pragma unroll
        for (int j = 0; j < 16; j++) o[j] = fmaf(ak, sW[k * 16 + j], o[j]);
    }

    float4* op = (float4*)(out + (long long)n * 16);
#pragma unroll
    for (int q = 0; q < 4; q++)
        op[q] = make_float4(o[q * 4], o[q * 4 + 1], o[q * 4 + 2], o[q * 4 + 3]);
}

// ---------------------------------------------------------------------------
extern "C" void kernel_launch(void* const* d_in, const int* in_sizes, int n_in,
                              void* d_out, int out_size) {
    const float* x   = (const float*)d_in[0];
    const void*  ei  = d_in[1];
    const float* W1  = (const float*)d_in[2];
    const float* b1  = (const float*)d_in[3];
    const float* W2  = (const float*)d_in[4];
    const float* b2  = (const float*)d_in[5];
    float* out = (float*)d_out;

    int N = in_sizes[0] / 128;
    int E = in_sizes[1] / 2;

    const int T = 256;
    int nb_N = (N + T - 1) / T;
    int nb_E = (E + T - 1) / T;
    int nb_W = (N * 32 + T - 1) / T;  // warp per node

    k_detect<<<1, 32>>>(ei, N);
    k_deg_init<<<nb_N, T>>>(N);
    k_convert_deg<<<nb_E, T>>>(ei, E);
    k_gemm1<<<nb_W, T>>>(x, W1, N);
    k_sc1<<<nb_E, T>>>(E);
    k_mid<<<nb_N, T>>>(b1, N);
    k_sc2<<<nb_E, T>>>(E);
    k_out<<<W2 ? nb_N : nb_N, T>>>(W2, b2, out, N);
}

// round 3
// speedup vs baseline: 1.7256x; 1.4501x over previous
#include <cuda_runtime.h>

// Problem constants (fixed by the dataset): N=200000, E=6400000, F: 128 -> 8 -> 16
#define NMAX 200000
#define EMAX 6400000

// Scratch (no cudaMalloc allowed)
__device__ float g_dis[NMAX];         // degree, then deg^-1/2 in place
__device__ float g_h[NMAX * 8];       // x @ W1
__device__ float g_agg[NMAX * 8];     // layer-1 aggregation
__device__ float g_r[NMAX * 8];       // relu(agg1 + b1)
__device__ float g_agg2[NMAX * 8];    // layer-2 aggregation (8-dim, pre-W2)
__device__ int2  g_edge[EMAX];        // packed (src, dst) int32
__device__ int   g_is64;              // edge_index dtype flag

// ---------------------------------------------------------------------------
// K0: detect whether edge_index is int64 or int32.
__global__ void k_detect(const void* ei, int N) {
    if (threadIdx.x == 0 && blockIdx.x == 0) {
        const long long* p = (const long long*)ei;
        int is64 = 1;
#pragma unroll
        for (int i = 0; i < 8; i++) {
            long long v = p[i];
            if (v < 0 || v >= (long long)N) is64 = 0;
        }
        g_is64 = is64;
    }
}

__global__ void k_deg_init(int N) {
    int i = blockIdx.x * blockDim.x + threadIdx.x;
    if (i < N) g_dis[i] = 1.0f;   // self-loop
}

// K1: convert indices to packed int2 once + degree scatter.
__global__ void k_convert_deg(const void* ei, int E) {
    int e = blockIdx.x * blockDim.x + threadIdx.x;
    if (e >= E) return;
    int is64 = g_is64;
    int s, d;
    if (is64) {
        s = (int)((const long long*)ei)[e];
        d = (int)((const long long*)ei)[(long long)E + e];
    } else {
        s = ((const int*)ei)[e];
        d = ((const int*)ei)[E + e];
    }
    g_edge[e] = make_int2(s, d);
    atomicAdd(&g_dis[d], 1.0f);
}

// ---------------------------------------------------------------------------
// K2: h = x @ W1 (N x 128)@(128 x 8). Warp per node, grid-stride.
// Lane (cg = lane>>2, fp = lane&3): cg owns 16 x-columns, fp owns 2 features.
// W slice (16 cols x 2 feats = 32 floats) lives in REGISTERS, loaded once per
// warp. Reduction is 3 shfl levels (over cg only) instead of 5x8 = 40 shfls.
// Fused: dis = rsqrt(deg) in place, agg1 = h * dis^2 (self-loop init).
__global__ void k_gemm1(const float* __restrict__ x, const float* __restrict__ W1, int N) {
    int lane = threadIdx.x & 31;
    int cg   = lane >> 2;       // 0..7: column group (16 columns)
    int fp   = lane & 3;        // 0..3: feature pair (2 features)

    // Preload W slice into registers: w2[i*4+k] = W1[(cg*16+i*4+k)][fp*2 .. +1]
    float2 w2[16];
#pragma unroll
    for (int c = 0; c < 16; c++)
        w2[c] = *(const float2*)&W1[(cg * 16 + c) * 8 + fp * 2];

    int warp  = (blockIdx.x * blockDim.x + threadIdx.x) >> 5;
    int nwarp = (gridDim.x * blockDim.x) >> 5;

    for (int n = warp; n < N; n += nwarp) {
        const float4* xr = (const float4*)(x + (long long)n * 128);
        float acc0 = 0.0f, acc1 = 0.0f;
#pragma unroll
        for (int i = 0; i < 4; i++) {
            float4 xv = xr[cg * 4 + i];
            float2 wa = w2[i * 4 + 0], wb = w2[i * 4 + 1];
            float2 wc = w2[i * 4 + 2], wd = w2[i * 4 + 3];
            acc0 = fmaf(xv.x, wa.x, acc0); acc1 = fmaf(xv.x, wa.y, acc1);
            acc0 = fmaf(xv.y, wb.x, acc0); acc1 = fmaf(xv.y, wb.y, acc1);
            acc0 = fmaf(xv.z, wc.x, acc0); acc1 = fmaf(xv.z, wc.y, acc1);
            acc0 = fmaf(xv.w, wd.x, acc0); acc1 = fmaf(xv.w, wd.y, acc1);
        }
        // Reduce across the 8 cg lanes (stride-4 lanes share fp).
#pragma unroll
        for (int off = 16; off >= 4; off >>= 1) {
            acc0 += __shfl_xor_sync(0xffffffffu, acc0, off);
            acc1 += __shfl_xor_sync(0xffffffffu, acc1, off);
        }

        float r = 0.0f;
        if (lane == 0) {
            r = rsqrtf(g_dis[n]);
            g_dis[n] = r;          // in place: deg -> deg^-1/2
        }
        r = __shfl_sync(0xffffffffu, r, 0);
        float s2 = r * r;

        if (lane < 4) {
            *(float2*)&g_h[(long long)n * 8 + fp * 2]   = make_float2(acc0, acc1);
            *(float2*)&g_agg[(long long)n * 8 + fp * 2] = make_float2(acc0 * s2, acc1 * s2);
        }
    }
}

// ---------------------------------------------------------------------------
__device__ __forceinline__ void red_v4(float* p, float a, float b, float c, float d) {
    asm volatile("red.global.add.v4.f32 [%0], {%1, %2, %3, %4};"
                 :: "l"(p), "f"(a), "f"(b), "f"(c), "f"(d) : "memory");
}

// Shared 8-dim edge scatter body: dst_feat[d] += src_feat[s] * dis[s]*dis[d]
__device__ __forceinline__ void scatter8(const float* __restrict__ src_feat,
                                         float* __restrict__ dst_feat, int E) {
    int e = blockIdx.x * blockDim.x + threadIdx.x;
    if (e >= E) return;
    int2 sd = g_edge[e];
    float w = g_dis[sd.x] * g_dis[sd.y];
    const float4* hp = (const float4*)(src_feat + (long long)sd.x * 8);
    float4 a = hp[0], b = hp[1];
    float* o = dst_feat + (long long)sd.y * 8;
    red_v4(o,     a.x * w, a.y * w, a.z * w, a.w * w);
    red_v4(o + 4, b.x * w, b.y * w, b.z * w, b.w * w);
}

__global__ void k_sc1(int E) { scatter8(g_h, g_agg, E); }
__global__ void k_sc2(int E) { scatter8(g_r, g_agg2, E); }

// ---------------------------------------------------------------------------
// K3: r = relu(agg1 + b1); agg2 self-loop init: agg2 = r * dis^2.
__global__ void k_mid(const float* __restrict__ b1, int N) {
    __shared__ float sb1[8];
    if (threadIdx.x < 8) sb1[threadIdx.x] = b1[threadIdx.x];
    __syncthreads();

    int n = blockIdx.x * blockDim.x + threadIdx.x;
    if (n >= N) return;

    const float4* ap = (const float4*)(g_agg + (long long)n * 8);
    float4 u = ap[0], v = ap[1];
    float4 r0 = make_float4(fmaxf(u.x + sb1[0], 0.0f), fmaxf(u.y + sb1[1], 0.0f),
                            fmaxf(u.z + sb1[2], 0.0f), fmaxf(u.w + sb1[3], 0.0f));
    float4 r1 = make_float4(fmaxf(v.x + sb1[4], 0.0f), fmaxf(v.y + sb1[5], 0.0f),
                            fmaxf(v.z + sb1[6], 0.0f), fmaxf(v.w + sb1[7], 0.0f));
    float4* rp = (float4*)(g_r + (long long)n * 8);
    rp[0] = r0; rp[1] = r1;

    float dis = g_dis[n];
    float s2 = dis * dis;
    float4* a2 = (float4*)(g_agg2 + (long long)n * 8);
    a2[0] = make_float4(r0.x * s2, r0.y * s2, r0.z * s2, r0.w * s2);
    a2[1] = make_float4(r1.x * s2, r1.y * s2, r1.z * s2, r1.w * s2);
}

// ---------------------------------------------------------------------------
// K4: out = agg2 @ W2 + b2   (W2 commuted past the aggregation)
__global__ void k_out(const float* __restrict__ W2, const float* __restrict__ b2,
                      float* __restrict__ out, int N) {
    __shared__ float sW[8 * 16];
    __shared__ float sb2[16];
    if (threadIdx.x < 128) sW[threadIdx.x] = W2[threadIdx.x];
    if (threadIdx.x < 16) sb2[threadIdx.x] = b2[threadIdx.x];
    __syncthreads();

    int n = blockIdx.x * blockDim.x + threadIdx.x;
    if (n >= N) return;

    const float4* ap = (const float4*)(g_agg2 + (long long)n * 8);
    float4 u = ap[0], v = ap[1];
    float a[8] = {u.x, u.y, u.z, u.w, v.x, v.y, v.z, v.w};

    float o[16];
#pragma unroll
    for (int j = 0; j < 16; j++) o[j] = sb2[j];
#pragma unroll
    for (int k = 0; k < 8; k++) {
        float ak = a[k];
#pragma unroll
        for (int j = 0; j < 16; j++) o[j] = fmaf(ak, sW[k * 16 + j], o[j]);
    }

    float4* op = (float4*)(out + (long long)n * 16);
#pragma unroll
    for (int q = 0; q < 4; q++)
        op[q] = make_float4(o[q * 4], o[q * 4 + 1], o[q * 4 + 2], o[q * 4 + 3]);
}

// ---------------------------------------------------------------------------
extern "C" void kernel_launch(void* const* d_in, const int* in_sizes, int n_in,
                              void* d_out, int out_size) {
    const float* x   = (const float*)d_in[0];
    const void*  ei  = d_in[1];
    const float* W1  = (const float*)d_in[2];
    const float* b1  = (const float*)d_in[3];
    const float* W2  = (const float*)d_in[4];
    const float* b2  = (const float*)d_in[5];
    float* out = (float*)d_out;

    int N = in_sizes[0] / 128;
    int E = in_sizes[1] / 2;

    const int T = 256;
    int nb_N = (N + T - 1) / T;
    int nb_E = (E + T - 1) / T;

    k_detect<<<1, 32>>>(ei, N);
    k_deg_init<<<nb_N, T>>>(N);
    k_convert_deg<<<nb_E, T>>>(ei, E);
    k_gemm1<<<1184, T>>>(x, W1, N);   // grid-stride, ~21 nodes/warp
    k_sc1<<<nb_E, T>>>(E);
    k_mid<<<nb_N, T>>>(b1, N);
    k_sc2<<<nb_E, T>>>(E);
    k_out<<<nb_N, T>>>(W2, b2, out, N);
}

// round 4
// speedup vs baseline: 2.2894x; 1.3268x over previous
#include <cuda_runtime.h>

// Problem constants (fixed by the dataset): N=200000, E=6400000, F: 128 -> 8 -> 16
#define NMAX 200000
#define EMAX 6400000

// Scratch (no cudaMalloc allowed)
__device__ float g_deg[NMAX];         // degree (float counts)
__device__ float g_dis[NMAX];         // deg^-1/2
__device__ float g_h[NMAX * 8];       // (x @ W1) * dis[src]   (pre-scaled!)
__device__ float g_agg[NMAX * 8];     // layer-1 unweighted aggregation
__device__ float g_r[NMAX * 8];       // relu(...) * dis[src]  (pre-scaled!)
__device__ float g_agg2[NMAX * 8];    // layer-2 unweighted aggregation
__device__ int2  g_edge[EMAX];        // packed (src, dst) int32
__device__ int   g_is64;              // edge_index dtype flag

// ---------------------------------------------------------------------------
// K0: detect whether edge_index is int64 or int32.
__global__ void k_detect(const void* ei, int N) {
    if (threadIdx.x == 0 && blockIdx.x == 0) {
        const long long* p = (const long long*)ei;
        int is64 = 1;
#pragma unroll
        for (int i = 0; i < 8; i++) {
            long long v = p[i];
            if (v < 0 || v >= (long long)N) is64 = 0;
        }
        g_is64 = is64;
    }
}

__global__ void k_deg_init(int N) {
    int i = blockIdx.x * blockDim.x + threadIdx.x;
    if (i < N) g_deg[i] = 1.0f;   // self-loop
}

// ---------------------------------------------------------------------------
// K1: convert indices to packed int2 (2 edges/thread) + degree scatter.
__global__ void k_convert_deg(const void* ei, int E) {
    int t = blockIdx.x * blockDim.x + threadIdx.x;   // over E/2 pairs
    int e = t * 2;
    if (e >= E) return;
    int is64 = g_is64;
    int s0, d0, s1, d1;
    if (is64) {
        longlong2 sv = ((const longlong2*)ei)[t];
        longlong2 dv = *(const longlong2*)((const long long*)ei + E + e);
        s0 = (int)sv.x; s1 = (int)sv.y;
        d0 = (int)dv.x; d1 = (int)dv.y;
    } else {
        int2 sv = *(const int2*)((const int*)ei + e);
        int2 dv = *(const int2*)((const int*)ei + E + e);
        s0 = sv.x; s1 = sv.y;
        d0 = dv.x; d1 = dv.y;
    }
    *(int4*)&g_edge[e] = make_int4(s0, d0, s1, d1);
    atomicAdd(&g_deg[d0], 1.0f);
    atomicAdd(&g_deg[d1], 1.0f);
}

// ---------------------------------------------------------------------------
// K2: h_scaled = (x @ W1) * dis. Warp per 2 nodes, grid-stride.
// Lane (cg = lane>>2, fp = lane&3): cg owns 16 x-columns, fp owns 2 features.
// W slice (16x2) in registers. 8 outstanding LDG.128 per warp iteration.
// Also: dis = rsqrt(deg) stored once, agg init = h_scaled (self-loop term).
__global__ void k_gemm1(const float* __restrict__ x, const float* __restrict__ W1, int N) {
    int lane = threadIdx.x & 31;
    int cg   = lane >> 2;
    int fp   = lane & 3;

    float2 w2[16];
#pragma unroll
    for (int c = 0; c < 16; c++)
        w2[c] = *(const float2*)&W1[(cg * 16 + c) * 8 + fp * 2];

    int warp  = (blockIdx.x * blockDim.x + threadIdx.x) >> 5;
    int nwarp = (gridDim.x * blockDim.x) >> 5;

    for (int n0 = warp * 2; n0 < N; n0 += nwarp * 2) {
        int n1 = n0 + 1;
        bool has1 = (n1 < N);

        const float4* xr0 = (const float4*)(x + (long long)n0 * 128);
        const float4* xr1 = (const float4*)(x + (long long)(has1 ? n1 : n0) * 128);

        float4 xa[4], xb[4];
#pragma unroll
        for (int i = 0; i < 4; i++) xa[i] = xr0[cg * 4 + i];
#pragma unroll
        for (int i = 0; i < 4; i++) xb[i] = xr1[cg * 4 + i];

        float a0 = 0.f, a1 = 0.f, b0 = 0.f, b1 = 0.f;
#pragma unroll
        for (int i = 0; i < 4; i++) {
            float2 wa = w2[i * 4 + 0], wb = w2[i * 4 + 1];
            float2 wc = w2[i * 4 + 2], wd = w2[i * 4 + 3];
            a0 = fmaf(xa[i].x, wa.x, a0); a1 = fmaf(xa[i].x, wa.y, a1);
            a0 = fmaf(xa[i].y, wb.x, a0); a1 = fmaf(xa[i].y, wb.y, a1);
            a0 = fmaf(xa[i].z, wc.x, a0); a1 = fmaf(xa[i].z, wc.y, a1);
            a0 = fmaf(xa[i].w, wd.x, a0); a1 = fmaf(xa[i].w, wd.y, a1);
            b0 = fmaf(xb[i].x, wa.x, b0); b1 = fmaf(xb[i].x, wa.y, b1);
            b0 = fmaf(xb[i].y, wb.x, b0); b1 = fmaf(xb[i].y, wb.y, b1);
            b0 = fmaf(xb[i].z, wc.x, b0); b1 = fmaf(xb[i].z, wc.y, b1);
            b0 = fmaf(xb[i].w, wd.x, b0); b1 = fmaf(xb[i].w, wd.y, b1);
        }
#pragma unroll
        for (int off = 16; off >= 4; off >>= 1) {
            a0 += __shfl_xor_sync(0xffffffffu, a0, off);
            a1 += __shfl_xor_sync(0xffffffffu, a1, off);
            b0 += __shfl_xor_sync(0xffffffffu, b0, off);
            b1 += __shfl_xor_sync(0xffffffffu, b1, off);
        }

        float r = 0.0f;
        if (lane < 2) {
            int nn = n0 + lane;
            if (nn < N) {
                r = rsqrtf(g_deg[nn]);
                g_dis[nn] = r;
            }
        }
        float r0 = __shfl_sync(0xffffffffu, r, 0);
        float r1 = __shfl_sync(0xffffffffu, r, 1);

        if (lane < 4) {
            float2 v0 = make_float2(a0 * r0, a1 * r0);
            *(float2*)&g_h[(long long)n0 * 8 + fp * 2]   = v0;
            *(float2*)&g_agg[(long long)n0 * 8 + fp * 2] = v0;
            if (has1) {
                float2 v1 = make_float2(b0 * r1, b1 * r1);
                *(float2*)&g_h[(long long)n1 * 8 + fp * 2]   = v1;
                *(float2*)&g_agg[(long long)n1 * 8 + fp * 2] = v1;
            }
        }
    }
}

// ---------------------------------------------------------------------------
__device__ __forceinline__ void red_v4(float* p, float4 v) {
    asm volatile("red.global.add.v4.f32 [%0], {%1, %2, %3, %4};"
                 :: "l"(p), "f"(v.x), "f"(v.y), "f"(v.z), "f"(v.w) : "memory");
}

// Unweighted 8-dim edge scatter, 2 edges per thread:
//   dst_feat[d] += src_feat[s]     (normalization hoisted to node passes)
__device__ __forceinline__ void scatter8(const float* __restrict__ src_feat,
                                         float* __restrict__ dst_feat, int E) {
    int t = blockIdx.x * blockDim.x + threadIdx.x;
    int e = t * 2;
    if (e >= E) return;
    int4 sd = *(const int4*)&g_edge[e];   // (s0, d0, s1, d1)

    const float4* h0 = (const float4*)(src_feat + (long long)sd.x * 8);
    const float4* h1 = (const float4*)(src_feat + (long long)sd.z * 8);
    float4 a0 = h0[0], a1 = h0[1];
    float4 b0 = h1[0], b1 = h1[1];

    float* o0 = dst_feat + (long long)sd.y * 8;
    float* o1 = dst_feat + (long long)sd.w * 8;
    red_v4(o0,     a0);
    red_v4(o0 + 4, a1);
    red_v4(o1,     b0);
    red_v4(o1 + 4, b1);
}

__global__ void k_sc1(int E) { scatter8(g_h, g_agg, E); }
__global__ void k_sc2(int E) { scatter8(g_r, g_agg2, E); }

// ---------------------------------------------------------------------------
// K3: r = relu(agg * dis + b1); r_scaled = r * dis; agg2 init = r_scaled.
__global__ void k_mid(const float* __restrict__ b1, int N) {
    __shared__ float sb1[8];
    if (threadIdx.x < 8) sb1[threadIdx.x] = b1[threadIdx.x];
    __syncthreads();

    int n = blockIdx.x * blockDim.x + threadIdx.x;
    if (n >= N) return;

    float dis = g_dis[n];
    const float4* ap = (const float4*)(g_agg + (long long)n * 8);
    float4 u = ap[0], v = ap[1];
    float4 r0 = make_float4(fmaxf(fmaf(u.x, dis, sb1[0]), 0.0f) * dis,
                            fmaxf(fmaf(u.y, dis, sb1[1]), 0.0f) * dis,
                            fmaxf(fmaf(u.z, dis, sb1[2]), 0.0f) * dis,
                            fmaxf(fmaf(u.w, dis, sb1[3]), 0.0f) * dis);
    float4 r1 = make_float4(fmaxf(fmaf(v.x, dis, sb1[4]), 0.0f) * dis,
                            fmaxf(fmaf(v.y, dis, sb1[5]), 0.0f) * dis,
                            fmaxf(fmaf(v.z, dis, sb1[6]), 0.0f) * dis,
                            fmaxf(fmaf(v.w, dis, sb1[7]), 0.0f) * dis);
    float4* rp = (float4*)(g_r + (long long)n * 8);
    float4* a2 = (float4*)(g_agg2 + (long long)n * 8);
    rp[0] = r0; rp[1] = r1;
    a2[0] = r0; a2[1] = r1;
}

// ---------------------------------------------------------------------------
// K4: out = (agg2 * dis) @ W2 + b2
__global__ void k_out(const float* __restrict__ W2, const float* __restrict__ b2,
                      float* __restrict__ out, int N) {
    __shared__ float sW[8 * 16];
    __shared__ float sb2[16];
    if (threadIdx.x < 128) sW[threadIdx.x] = W2[threadIdx.x];
    if (threadIdx.x < 16) sb2[threadIdx.x] = b2[threadIdx.x];
    __syncthreads();

    int n = blockIdx.x * blockDim.x + threadIdx.x;
    if (n >= N) return;

    float dis = g_dis[n];
    const float4* ap = (const float4*)(g_agg2 + (long long)n * 8);
    float4 u = ap[0], v = ap[1];
    float a[8] = {u.x * dis, u.y * dis, u.z * dis, u.w * dis,
                  v.x * dis, v.y * dis, v.z * dis, v.w * dis};

    float o[16];
#pragma unroll
    for (int j = 0; j < 16; j++) o[j] = sb2[j];
#pragma unroll
    for (int k = 0; k < 8; k++) {
        float ak = a[k];
#pragma unroll
        for (int j = 0; j < 16; j++) o[j] = fmaf(ak, sW[k * 16 + j], o[j]);
    }

    float4* op = (float4*)(out + (long long)n * 16);
#pragma unroll
    for (int q = 0; q < 4; q++)
        op[q] = make_float4(o[q * 4], o[q * 4 + 1], o[q * 4 + 2], o[q * 4 + 3]);
}

// ---------------------------------------------------------------------------
extern "C" void kernel_launch(void* const* d_in, const int* in_sizes, int n_in,
                              void* d_out, int out_size) {
    const float* x   = (const float*)d_in[0];
    const void*  ei  = d_in[1];
    const float* W1  = (const float*)d_in[2];
    const float* b1  = (const float*)d_in[3];
    const float* W2  = (const float*)d_in[4];
    const float* b2  = (const float*)d_in[5];
    float* out = (float*)d_out;

    int N = in_sizes[0] / 128;
    int E = in_sizes[1] / 2;

    const int T = 256;
    int nb_N  = (N + T - 1) / T;
    int nb_E2 = (E / 2 + T - 1) / T;

    k_detect<<<1, 32>>>(ei, N);
    k_deg_init<<<nb_N, T>>>(N);
    k_convert_deg<<<nb_E2, T>>>(ei, E);
    k_gemm1<<<1184, T>>>(x, W1, N);
    k_sc1<<<nb_E2, T>>>(E);
    k_mid<<<nb_N, T>>>(b1, N);
    k_sc2<<<nb_E2, T>>>(E);
    k_out<<<nb_N, T>>>(W2, b2, out, N);
}